// round 1
// baseline (speedup 1.0000x reference)
#include <cuda_runtime.h>
#include <cuda_bf16.h>

#define NN   100000
#define FIN  512
#define HID  256
#define CC   40
#define EE   1600000
#define KIT  10
#define ALPHAF 0.1f

// ---- scratch (static device allocations; no runtime alloc) ----
__device__ float g_h1[NN * HID];    // relu(x@W1+b1)            102.4 MB
__device__ float g_h [NN * CC];     // relu(h1@W2+b2)            16 MB
__device__ float g_z0[NN * CC];     // ping                      16 MB
__device__ float g_z1[NN * CC];     // pong                      16 MB
__device__ float g_deg [NN];
__device__ float g_dinv[NN];
__device__ float g_w  [EE];         // edge weights               6.4 MB

// ---------------- GEMM1: h1 = relu(x @ W1 + b1)  [N,512]x[512,256] ----------------
__global__ void gemm_relu_1(const float* __restrict__ X,
                            const float* __restrict__ W,
                            const float* __restrict__ bias) {
    __shared__ float As[16][64 + 4];   // [k][m]
    __shared__ float Bs[16][64 + 4];   // [k][n]
    const int bm = blockIdx.y * 64;
    const int bn = blockIdx.x * 64;
    const int tid = threadIdx.x;           // 0..255
    const int tx = tid % 16, ty = tid / 16;

    float acc[4][4];
#pragma unroll
    for (int i = 0; i < 4; i++)
#pragma unroll
        for (int j = 0; j < 4; j++) acc[i][j] = 0.f;

    for (int k0 = 0; k0 < FIN; k0 += 16) {
        // A tile: 64 rows x 16 k
#pragma unroll
        for (int i = tid; i < 64 * 16; i += 256) {
            int m = i / 16, k = i % 16;
            int row = bm + m;
            As[k][m] = (row < NN) ? X[(size_t)row * FIN + k0 + k] : 0.f;
        }
        // B tile: 16 k x 64 cols
#pragma unroll
        for (int i = tid; i < 16 * 64; i += 256) {
            int k = i / 64, n = i % 64;
            Bs[k][n] = W[(size_t)(k0 + k) * HID + bn + n];
        }
        __syncthreads();
#pragma unroll
        for (int k = 0; k < 16; k++) {
            float a[4], b[4];
#pragma unroll
            for (int i = 0; i < 4; i++) a[i] = As[k][ty * 4 + i];
#pragma unroll
            for (int j = 0; j < 4; j++) b[j] = Bs[k][tx * 4 + j];
#pragma unroll
            for (int i = 0; i < 4; i++)
#pragma unroll
                for (int j = 0; j < 4; j++) acc[i][j] += a[i] * b[j];
        }
        __syncthreads();
    }
#pragma unroll
    for (int i = 0; i < 4; i++) {
        int row = bm + ty * 4 + i;
        if (row >= NN) continue;
#pragma unroll
        for (int j = 0; j < 4; j++) {
            int col = bn + tx * 4 + j;
            float v = acc[i][j] + bias[col];
            g_h1[(size_t)row * HID + col] = fmaxf(v, 0.f);
        }
    }
}

// ---------------- GEMM2: h = relu(h1 @ W2 + b2)  [N,256]x[256,40] ----------------
// blockDim = (40, 8): x = output class, y = row within block of 8 rows
__global__ void gemm_relu_2(const float* __restrict__ W2,
                            const float* __restrict__ b2) {
    __shared__ float W2s[HID * CC];       // 40 KB
    const int tid = threadIdx.y * 40 + threadIdx.x;
    for (int i = tid; i < HID * CC; i += 40 * 8)
        W2s[i] = W2[i];
    __syncthreads();

    const int row = blockIdx.x * 8 + threadIdx.y;
    if (row >= NN) return;
    const int col = threadIdx.x;
    const float* hrow = &g_h1[(size_t)row * HID];
    float acc = 0.f;
#pragma unroll 8
    for (int k = 0; k < HID; k++)
        acc += hrow[k] * W2s[k * CC + col];
    acc += b2[col];
    g_h[(size_t)row * CC + col] = fmaxf(acc, 0.f);
}

// ---------------- degree / weights ----------------
__global__ void init_deg() {
    int i = blockIdx.x * blockDim.x + threadIdx.x;
    if (i < NN) g_deg[i] = 1.0f;          // self loop
}
__global__ void count_deg(const int* __restrict__ dst) {
    int e = blockIdx.x * blockDim.x + threadIdx.x;
    if (e < EE) atomicAdd(&g_deg[dst[e]], 1.0f);
}
__global__ void calc_dinv() {
    int i = blockIdx.x * blockDim.x + threadIdx.x;
    if (i < NN) g_dinv[i] = rsqrtf(g_deg[i]);
}
__global__ void calc_w(const int* __restrict__ src, const int* __restrict__ dst) {
    int e = blockIdx.x * blockDim.x + threadIdx.x;
    if (e < EE) g_w[e] = g_dinv[src[e]] * g_dinv[dst[e]];
}

// ---------------- propagation ----------------
__global__ void zero_buf(float* __restrict__ p, int n) {
    int i = blockIdx.x * blockDim.x + threadIdx.x;
    if (i < n) p[i] = 0.f;
}

// one thread per (edge, 4-channel group): E * 10 threads
__global__ void scatter_edges(const float* __restrict__ z,
                              float* __restrict__ agg,
                              const int* __restrict__ src,
                              const int* __restrict__ dst) {
    long long tid = (long long)blockIdx.x * blockDim.x + threadIdx.x;
    if (tid >= (long long)EE * 10) return;
    int e = (int)(tid / 10);
    int q = (int)(tid % 10);
    int s = src[e];
    int d = dst[e];
    float w = g_w[e];
    const float4* z4 = reinterpret_cast<const float4*>(z);
    float4 v = z4[(size_t)s * 10 + q];
    float* dstp = &agg[(size_t)d * CC + q * 4];
    atomicAdd(dstp + 0, w * v.x);
    atomicAdd(dstp + 1, w * v.y);
    atomicAdd(dstp + 2, w * v.z);
    atomicAdd(dstp + 3, w * v.w);
}

// z_next[i] = (1-a) * (agg[i] + dinv[node]^2 * z_old[i]) + a * h[i]
__global__ void combine(const float* __restrict__ agg,
                        const float* __restrict__ zold,
                        float* __restrict__ znext) {
    int i = blockIdx.x * blockDim.x + threadIdx.x;
    if (i >= NN * CC) return;
    int node = i / CC;
    float di = g_dinv[node];
    float selfw = di * di;
    float a = agg[i] + selfw * zold[i];
    znext[i] = (1.0f - ALPHAF) * a + ALPHAF * g_h[i];
}

// ---------------- launch ----------------
extern "C" void kernel_launch(void* const* d_in, const int* in_sizes, int n_in,
                              void* d_out, int out_size) {
    const float* x  = (const float*)d_in[0];
    const int*   ei = (const int*)  d_in[1];
    const float* W1 = (const float*)d_in[2];
    const float* b1 = (const float*)d_in[3];
    const float* W2 = (const float*)d_in[4];
    const float* b2 = (const float*)d_in[5];
    float* out = (float*)d_out;

    const int* src = ei;
    const int* dst = ei + EE;

    float *p_h1, *p_h, *p_z0, *p_z1;
    cudaGetSymbolAddress((void**)&p_h1, g_h1);
    cudaGetSymbolAddress((void**)&p_h,  g_h);
    cudaGetSymbolAddress((void**)&p_z0, g_z0);
    cudaGetSymbolAddress((void**)&p_z1, g_z1);

    // MLP
    dim3 g1((HID + 63) / 64, (NN + 63) / 64);
    gemm_relu_1<<<g1, 256>>>(x, W1, b1);
    gemm_relu_2<<<(NN + 7) / 8, dim3(40, 8)>>>(W2, b2);

    // normalization
    init_deg<<<(NN + 255) / 256, 256>>>();
    count_deg<<<(EE + 255) / 256, 256>>>(dst);
    calc_dinv<<<(NN + 255) / 256, 256>>>();
    calc_w<<<(EE + 255) / 256, 256>>>(src, dst);

    // K power-iteration steps, ping-pong g_z0 / g_z1; z_cur starts at g_h
    const int NC = NN * CC;
    const long long SCAT = (long long)EE * 10;
    int scat_blocks = (int)((SCAT + 255) / 256);

    for (int it = 0; it < KIT; it++) {
        float* aggb = (it % 2 == 0) ? p_z0 : p_z1;
        const float* zcur = (it == 0) ? p_h : ((it % 2 == 0) ? p_z1 : p_z0);
        float* znext = (it == KIT - 1) ? out : aggb;

        zero_buf<<<(NC + 255) / 256, 256>>>(aggb, NC);
        scatter_edges<<<scat_blocks, 256>>>(zcur, aggb, src, dst);
        combine<<<(NC + 255) / 256, 256>>>(aggb, zcur, znext);
    }
}

// round 2
// speedup vs baseline: 1.9763x; 1.9763x over previous
#include <cuda_runtime.h>
#include <cuda_bf16.h>

#define NN   100000
#define FIN  512
#define HID  256
#define CC   40
#define EE   1600000
#define KIT  10
#define ALPHAF 0.1f

// ---- static device scratch ----
__device__ float g_h1[NN * HID];        // relu(x@W1+b1)
__device__ float g_h [NN * CC];         // relu(h1@W2+b2)
__device__ float g_z0[NN * CC];
__device__ float g_z1[NN * CC];
__device__ float g_dinv[NN];
__device__ int   g_cnt[NN];
__device__ int   g_rowptr[NN + 1];
__device__ int   g_cursor[NN];
__device__ int   g_eidx[EE];            // CSR-by-dst: src node ids
__device__ float g_ew  [EE];            // CSR-by-dst: edge weights

// ================= GEMM1: h1 = relu(x @ W1 + b1)  [100000,512]x[512,256] =================
#define BM 128
#define BN 128
#define BK 8

__global__ __launch_bounds__(256, 2)
void sgemm_relu_1(const float* __restrict__ X,
                  const float* __restrict__ W,
                  const float* __restrict__ bias) {
    __shared__ float As[BK][BM];    // transposed A tile
    __shared__ float Bs[BK][BN];

    const int bm = blockIdx.y * BM;
    const int bn = blockIdx.x * BN;
    const int tid = threadIdx.x;

    // A load: each thread one float4 along K. row = tid/2, k = (tid&1)*4
    const int arow = tid >> 1;
    const int ak   = (tid & 1) * 4;
    // B load: each thread one float4 along N. k = tid/32, col = (tid&31)*4
    const int bk   = tid >> 5;
    const int bcol = (tid & 31) * 4;

    const int tx = tid & 15;    // output col group
    const int ty = tid >> 4;    // output row group

    float acc[8][8];
#pragma unroll
    for (int i = 0; i < 8; i++)
#pragma unroll
        for (int j = 0; j < 8; j++) acc[i][j] = 0.f;

    for (int k0 = 0; k0 < FIN; k0 += BK) {
        // load A tile (transpose into As[k][m])
        {
            const int grow = bm + arow;
            float4 av = make_float4(0.f, 0.f, 0.f, 0.f);
            if (grow < NN)
                av = *reinterpret_cast<const float4*>(&X[(size_t)grow * FIN + k0 + ak]);
            As[ak + 0][arow] = av.x;
            As[ak + 1][arow] = av.y;
            As[ak + 2][arow] = av.z;
            As[ak + 3][arow] = av.w;
        }
        // load B tile
        {
            float4 bv = *reinterpret_cast<const float4*>(&W[(size_t)(k0 + bk) * HID + bn + bcol]);
            *reinterpret_cast<float4*>(&Bs[bk][bcol]) = bv;
        }
        __syncthreads();

#pragma unroll
        for (int k = 0; k < BK; k++) {
            float a[8], b[8];
            *reinterpret_cast<float4*>(&a[0]) = *reinterpret_cast<const float4*>(&As[k][ty * 8]);
            *reinterpret_cast<float4*>(&a[4]) = *reinterpret_cast<const float4*>(&As[k][ty * 8 + 4]);
            *reinterpret_cast<float4*>(&b[0]) = *reinterpret_cast<const float4*>(&Bs[k][tx * 8]);
            *reinterpret_cast<float4*>(&b[4]) = *reinterpret_cast<const float4*>(&Bs[k][tx * 8 + 4]);
#pragma unroll
            for (int i = 0; i < 8; i++)
#pragma unroll
                for (int j = 0; j < 8; j++) acc[i][j] += a[i] * b[j];
        }
        __syncthreads();
    }

    // epilogue: bias + relu, float4 stores
    float bv[8];
#pragma unroll
    for (int j = 0; j < 8; j++) bv[j] = bias[bn + tx * 8 + j];

#pragma unroll
    for (int i = 0; i < 8; i++) {
        int row = bm + ty * 8 + i;
        if (row >= NN) continue;
        float4 o0, o1;
        o0.x = fmaxf(acc[i][0] + bv[0], 0.f);
        o0.y = fmaxf(acc[i][1] + bv[1], 0.f);
        o0.z = fmaxf(acc[i][2] + bv[2], 0.f);
        o0.w = fmaxf(acc[i][3] + bv[3], 0.f);
        o1.x = fmaxf(acc[i][4] + bv[4], 0.f);
        o1.y = fmaxf(acc[i][5] + bv[5], 0.f);
        o1.z = fmaxf(acc[i][6] + bv[6], 0.f);
        o1.w = fmaxf(acc[i][7] + bv[7], 0.f);
        *reinterpret_cast<float4*>(&g_h1[(size_t)row * HID + bn + tx * 8])     = o0;
        *reinterpret_cast<float4*>(&g_h1[(size_t)row * HID + bn + tx * 8 + 4]) = o1;
    }
}

// ================= GEMM2: h = relu(h1 @ W2 + b2)  [N,256]x[256,40] =================
__global__ void gemm_relu_2(const float* __restrict__ W2,
                            const float* __restrict__ b2) {
    __shared__ float W2s[HID * CC];       // 40 KB
    const int tid = threadIdx.y * 40 + threadIdx.x;
    for (int i = tid; i < HID * CC; i += 40 * 8)
        W2s[i] = W2[i];
    __syncthreads();

    const int row = blockIdx.x * 8 + threadIdx.y;
    if (row >= NN) return;
    const int col = threadIdx.x;
    const float* hrow = &g_h1[(size_t)row * HID];
    float acc = 0.f;
#pragma unroll 8
    for (int k = 0; k < HID; k++)
        acc += hrow[k] * W2s[k * CC + col];
    acc += b2[col];
    g_h[(size_t)row * CC + col] = fmaxf(acc, 0.f);
}

// ================= degree / CSR build =================
__global__ void zero_cnt() {
    int i = blockIdx.x * blockDim.x + threadIdx.x;
    if (i < NN) g_cnt[i] = 0;
}
__global__ void count_deg(const int* __restrict__ dst) {
    int e = blockIdx.x * blockDim.x + threadIdx.x;
    if (e < EE) atomicAdd(&g_cnt[dst[e]], 1);
}
__global__ void calc_dinv() {
    int i = blockIdx.x * blockDim.x + threadIdx.x;
    if (i < NN) g_dinv[i] = rsqrtf((float)g_cnt[i] + 1.0f);   // +1 self loop
}
// single-block exclusive scan -> rowptr, cursor
__global__ void scan_rowptr() {
    __shared__ int s[1024];
    __shared__ int carry;
    const int tid = threadIdx.x;
    if (tid == 0) carry = 0;
    __syncthreads();
    for (int base = 0; base < NN; base += 1024) {
        int i = base + tid;
        int v = (i < NN) ? g_cnt[i] : 0;
        s[tid] = v;
        __syncthreads();
#pragma unroll
        for (int off = 1; off < 1024; off <<= 1) {
            int t = (tid >= off) ? s[tid - off] : 0;
            __syncthreads();
            s[tid] += t;
            __syncthreads();
        }
        if (i < NN) {
            int ex = carry + s[tid] - v;
            g_rowptr[i] = ex;
            g_cursor[i] = ex;
        }
        __syncthreads();
        if (tid == 0) carry += s[1023];
        __syncthreads();
    }
    if (tid == 0) g_rowptr[NN] = carry;
}
__global__ void fill_csr(const int* __restrict__ src, const int* __restrict__ dst) {
    int e = blockIdx.x * blockDim.x + threadIdx.x;
    if (e >= EE) return;
    int s = src[e];
    int d = dst[e];
    int pos = atomicAdd(&g_cursor[d], 1);
    g_eidx[pos] = s;
    g_ew[pos]   = g_dinv[s] * g_dinv[d];
}

// ================= fused propagation step =================
// 10 threads per node; thread q owns channels [4q, 4q+4)
__global__ __launch_bounds__(320)
void prop_step(const float* __restrict__ z,
               float* __restrict__ zn) {
    const int tid  = blockIdx.x * blockDim.x + threadIdx.x;
    const int node = tid / 10;
    const int q    = tid % 10;
    if (node >= NN) return;

    const int beg = g_rowptr[node];
    const int end = g_rowptr[node + 1];

    const float4* __restrict__ z4 = reinterpret_cast<const float4*>(z);

    float4 acc = make_float4(0.f, 0.f, 0.f, 0.f);
    for (int e = beg; e < end; e++) {
        const int   s = __ldg(&g_eidx[e]);
        const float w = __ldg(&g_ew[e]);
        float4 v = __ldg(&z4[(size_t)s * 10 + q]);
        acc.x += w * v.x;
        acc.y += w * v.y;
        acc.z += w * v.z;
        acc.w += w * v.w;
    }

    const float di = g_dinv[node];
    const float sw = di * di;
    const float4 zc = z4[(size_t)node * 10 + q];
    const float4 hh = reinterpret_cast<const float4*>(g_h)[(size_t)node * 10 + q];

    float4 o;
    o.x = (1.0f - ALPHAF) * (acc.x + sw * zc.x) + ALPHAF * hh.x;
    o.y = (1.0f - ALPHAF) * (acc.y + sw * zc.y) + ALPHAF * hh.y;
    o.z = (1.0f - ALPHAF) * (acc.z + sw * zc.z) + ALPHAF * hh.z;
    o.w = (1.0f - ALPHAF) * (acc.w + sw * zc.w) + ALPHAF * hh.w;
    reinterpret_cast<float4*>(zn)[(size_t)node * 10 + q] = o;
}

// ================= launch =================
extern "C" void kernel_launch(void* const* d_in, const int* in_sizes, int n_in,
                              void* d_out, int out_size) {
    const float* x  = (const float*)d_in[0];
    const int*   ei = (const int*)  d_in[1];
    const float* W1 = (const float*)d_in[2];
    const float* b1 = (const float*)d_in[3];
    const float* W2 = (const float*)d_in[4];
    const float* b2 = (const float*)d_in[5];
    float* out = (float*)d_out;

    const int* src = ei;
    const int* dst = ei + EE;

    float *p_h, *p_z0, *p_z1;
    cudaGetSymbolAddress((void**)&p_h,  g_h);
    cudaGetSymbolAddress((void**)&p_z0, g_z0);
    cudaGetSymbolAddress((void**)&p_z1, g_z1);

    // MLP
    dim3 g1(HID / BN, (NN + BM - 1) / BM);
    sgemm_relu_1<<<g1, 256>>>(x, W1, b1);
    gemm_relu_2<<<(NN + 7) / 8, dim3(40, 8)>>>(W2, b2);

    // CSR build (by destination)
    zero_cnt <<<(NN + 255) / 256, 256>>>();
    count_deg<<<(EE + 255) / 256, 256>>>(dst);
    calc_dinv<<<(NN + 255) / 256, 256>>>();
    scan_rowptr<<<1, 1024>>>();
    fill_csr <<<(EE + 255) / 256, 256>>>(src, dst);

    // K fused propagation steps (ping-pong)
    const int threads = NN * 10;
    const int blocks  = (threads + 319) / 320;
    for (int it = 0; it < KIT; it++) {
        const float* zcur = (it == 0) ? p_h : ((it & 1) ? p_z1 : p_z0);
        float* znext = (it == KIT - 1) ? out : ((it & 1) ? p_z0 : p_z1);
        prop_step<<<blocks, 320>>>(zcur, znext);
    }
}

// round 3
// speedup vs baseline: 2.5366x; 1.2835x over previous
#include <cuda_runtime.h>
#include <cuda_bf16.h>
#include <cstdint>

#define NN   100000
#define FIN  512
#define HID  256
#define CC   40
#define EE   1600000
#define KIT  10
#define ALPHAF 0.1f

// ---- static device scratch ----
__device__ float g_h1[NN * HID];        // relu(x@W1+b1)
__device__ float g_h [NN * CC];         // relu(h1@W2+b2)
__device__ float g_z0[NN * CC];
__device__ float g_z1[NN * CC];
__device__ float g_dinv[NN];
__device__ int   g_cnt[NN];
__device__ int   g_rowptr[NN + 1];
__device__ int   g_cursor[NN];
__device__ int   g_eidx[EE];            // CSR-by-dst: src node ids
__device__ float g_ew  [EE];            // CSR-by-dst: edge weights

// ===================== tensor-core GEMM1 =====================
// h1 = relu(x @ W1 + b1), [100000,512] x [512,256]
// bf16 split (hi+lo) x 3 products -> ~fp32 precision on tensor cores.
#define BM 128
#define BN 128
#define BK 32
#define SA 40      // A smem row stride (bf16 elems): 80B -> conflict-free ldmatrix
#define SB 136     // B smem row stride (bf16 elems): 272B -> conflict-free ldmatrix

__device__ __forceinline__ uint32_t smem_u32(const void* p) {
    return (uint32_t)__cvta_generic_to_shared(p);
}

__device__ __forceinline__ uint32_t pack_bf16(float a, float b) {
    __nv_bfloat162 t = __floats2bfloat162_rn(a, b);   // (lo=a, hi=b)
    return *reinterpret_cast<uint32_t*>(&t);
}

__device__ __forceinline__ void ldmatrix_x4(uint32_t* r, uint32_t addr) {
    asm volatile("ldmatrix.sync.aligned.m8n8.x4.shared.b16 {%0,%1,%2,%3}, [%4];"
                 : "=r"(r[0]), "=r"(r[1]), "=r"(r[2]), "=r"(r[3]) : "r"(addr));
}
__device__ __forceinline__ void ldmatrix_x2_trans(uint32_t* r, uint32_t addr) {
    asm volatile("ldmatrix.sync.aligned.m8n8.x2.trans.shared.b16 {%0,%1}, [%2];"
                 : "=r"(r[0]), "=r"(r[1]) : "r"(addr));
}
__device__ __forceinline__ void mma_bf16(float* c, const uint32_t* a, const uint32_t* b) {
    asm volatile("mma.sync.aligned.m16n8k16.row.col.f32.bf16.bf16.f32 "
                 "{%0,%1,%2,%3}, {%4,%5,%6,%7}, {%8,%9}, {%0,%1,%2,%3};"
                 : "+f"(c[0]), "+f"(c[1]), "+f"(c[2]), "+f"(c[3])
                 : "r"(a[0]), "r"(a[1]), "r"(a[2]), "r"(a[3]), "r"(b[0]), "r"(b[1]));
}

__global__ __launch_bounds__(256, 1)
void sgemm1_tc(const float* __restrict__ X,
               const float* __restrict__ W,
               const float* __restrict__ bias) {
    __shared__ __nv_bfloat16 Ah[BM * SA];
    __shared__ __nv_bfloat16 Al[BM * SA];
    __shared__ __nv_bfloat16 Bh[BK * SB];
    __shared__ __nv_bfloat16 Bl[BK * SB];

    const int tid  = threadIdx.x;
    const int lane = tid & 31;
    const int warp = tid >> 5;
    const int wm   = warp >> 2;     // 0..1 : 64-row slab
    const int wn   = warp & 3;      // 0..3 : 32-col slab
    const int bm   = blockIdx.y * BM;
    const int bn   = blockIdx.x * BN;

    // gmem load mapping
    const int xrow = tid >> 1;                 // 0..127
    const int xk   = (tid & 1) * 16;           // 0 or 16
    const int wk   = tid >> 3;                 // 0..31
    const int wn0  = (tid & 7) * 16;           // 0..112

    float4 xv[4], wv[4];
    const bool xrow_ok = (bm + xrow) < NN;
    const float* xptr = X + (size_t)(bm + xrow) * FIN + xk;
    const float* wptr = W + (size_t)wk * HID + bn + wn0;

    // prologue: load k-tile 0
#pragma unroll
    for (int j = 0; j < 4; j++) {
        xv[j] = xrow_ok ? *reinterpret_cast<const float4*>(xptr + j * 4)
                        : make_float4(0.f, 0.f, 0.f, 0.f);
        wv[j] = *reinterpret_cast<const float4*>(wptr + j * 4);
    }

    float acc[4][4][4];
#pragma unroll
    for (int i = 0; i < 4; i++)
#pragma unroll
        for (int j = 0; j < 4; j++)
#pragma unroll
            for (int k = 0; k < 4; k++) acc[i][j][k] = 0.f;

    // ldmatrix source addresses (per k16 sub-step via +offset)
    // A: groups of 8 lanes -> (row, kcol) quadrants of the 16x16 tile
    const int agrp = lane >> 3;
    const int arow_l = (agrp & 1) * 8 + (lane & 7);
    const int akcol  = (agrp >> 1) * 8;
    // B: lanes 0..15 -> rows k0..15 at col base
    const int bkrow = (lane & 15);

    for (int kt = 0; kt < FIN / BK; kt++) {
        // ---- store current regs -> smem (with bf16 hi/lo split) ----
        {
            uint32_t* ah = reinterpret_cast<uint32_t*>(&Ah[xrow * SA + xk]);
            uint32_t* al = reinterpret_cast<uint32_t*>(&Al[xrow * SA + xk]);
#pragma unroll
            for (int j = 0; j < 4; j++) {
                float f[4] = {xv[j].x, xv[j].y, xv[j].z, xv[j].w};
                float h[4], l[4];
#pragma unroll
                for (int q = 0; q < 4; q++) {
                    __nv_bfloat16 hb = __float2bfloat16_rn(f[q]);
                    h[q] = __bfloat162float(hb);
                    l[q] = f[q] - h[q];
                }
                ah[j * 2 + 0] = pack_bf16(h[0], h[1]);
                ah[j * 2 + 1] = pack_bf16(h[2], h[3]);
                al[j * 2 + 0] = pack_bf16(l[0], l[1]);
                al[j * 2 + 1] = pack_bf16(l[2], l[3]);
            }
            uint32_t* bh = reinterpret_cast<uint32_t*>(&Bh[wk * SB + wn0]);
            uint32_t* bl = reinterpret_cast<uint32_t*>(&Bl[wk * SB + wn0]);
#pragma unroll
            for (int j = 0; j < 4; j++) {
                float f[4] = {wv[j].x, wv[j].y, wv[j].z, wv[j].w};
                float h[4], l[4];
#pragma unroll
                for (int q = 0; q < 4; q++) {
                    __nv_bfloat16 hb = __float2bfloat16_rn(f[q]);
                    h[q] = __bfloat162float(hb);
                    l[q] = f[q] - h[q];
                }
                bh[j * 2 + 0] = pack_bf16(h[0], h[1]);
                bh[j * 2 + 1] = pack_bf16(h[2], h[3]);
                bl[j * 2 + 0] = pack_bf16(l[0], l[1]);
                bl[j * 2 + 1] = pack_bf16(l[2], l[3]);
            }
        }
        __syncthreads();

        // ---- prefetch next k-tile into regs (overlaps with mma below) ----
        if (kt + 1 < FIN / BK) {
            const float* xp = xptr + (kt + 1) * BK;
            const float* wp = wptr + (size_t)(kt + 1) * BK * HID;
#pragma unroll
            for (int j = 0; j < 4; j++) {
                xv[j] = xrow_ok ? *reinterpret_cast<const float4*>(xp + j * 4)
                                : make_float4(0.f, 0.f, 0.f, 0.f);
                wv[j] = *reinterpret_cast<const float4*>(wp + j * 4);
            }
        }

        // ---- compute 2 x k16 ----
#pragma unroll
        for (int ks = 0; ks < BK; ks += 16) {
            uint32_t a_h[4][4], a_l[4][4], b_h[4][2], b_l[4][2];
#pragma unroll
            for (int im = 0; im < 4; im++) {
                int mrow = wm * 64 + im * 16 + arow_l;
                uint32_t ad_h = smem_u32(&Ah[mrow * SA + ks + akcol]);
                uint32_t ad_l = smem_u32(&Al[mrow * SA + ks + akcol]);
                ldmatrix_x4(a_h[im], ad_h);
                ldmatrix_x4(a_l[im], ad_l);
            }
#pragma unroll
            for (int in_ = 0; in_ < 4; in_++) {
                int ncol = wn * 32 + in_ * 8;
                uint32_t bd_h = smem_u32(&Bh[(ks + bkrow) * SB + ncol]);
                uint32_t bd_l = smem_u32(&Bl[(ks + bkrow) * SB + ncol]);
                ldmatrix_x2_trans(b_h[in_], bd_h);
                ldmatrix_x2_trans(b_l[in_], bd_l);
            }
#pragma unroll
            for (int im = 0; im < 4; im++)
#pragma unroll
                for (int in_ = 0; in_ < 4; in_++) {
                    mma_bf16(acc[im][in_], a_h[im], b_h[in_]);
                    mma_bf16(acc[im][in_], a_h[im], b_l[in_]);
                    mma_bf16(acc[im][in_], a_l[im], b_h[in_]);
                }
        }
        __syncthreads();
    }

    // ---- epilogue: bias + relu ----
    const int r_in = lane >> 2;
    const int c_in = (lane & 3) * 2;
#pragma unroll
    for (int in_ = 0; in_ < 4; in_++) {
        int col = bn + wn * 32 + in_ * 8 + c_in;
        float b0 = bias[col], b1 = bias[col + 1];
#pragma unroll
        for (int im = 0; im < 4; im++) {
            int row0 = bm + wm * 64 + im * 16 + r_in;
            if (row0 < NN) {
                float2 o;
                o.x = fmaxf(acc[im][in_][0] + b0, 0.f);
                o.y = fmaxf(acc[im][in_][1] + b1, 0.f);
                *reinterpret_cast<float2*>(&g_h1[(size_t)row0 * HID + col]) = o;
            }
            int row1 = row0 + 8;
            if (row1 < NN) {
                float2 o;
                o.x = fmaxf(acc[im][in_][2] + b0, 0.f);
                o.y = fmaxf(acc[im][in_][3] + b1, 0.f);
                *reinterpret_cast<float2*>(&g_h1[(size_t)row1 * HID + col]) = o;
            }
        }
    }
}

// ================= GEMM2: h = relu(h1 @ W2 + b2)  [N,256]x[256,40] =================
__global__ void gemm_relu_2(const float* __restrict__ W2,
                            const float* __restrict__ b2) {
    __shared__ float W2s[HID * CC];       // 40 KB
    const int tid = threadIdx.y * 40 + threadIdx.x;
    for (int i = tid; i < HID * CC; i += 40 * 8)
        W2s[i] = W2[i];
    __syncthreads();

    const int row = blockIdx.x * 8 + threadIdx.y;
    if (row >= NN) return;
    const int col = threadIdx.x;
    const float* hrow = &g_h1[(size_t)row * HID];
    float acc = 0.f;
#pragma unroll 8
    for (int k = 0; k < HID; k++)
        acc += hrow[k] * W2s[k * CC + col];
    acc += b2[col];
    g_h[(size_t)row * CC + col] = fmaxf(acc, 0.f);
}

// ================= degree / CSR build =================
__global__ void zero_cnt() {
    int i = blockIdx.x * blockDim.x + threadIdx.x;
    if (i < NN) g_cnt[i] = 0;
}
__global__ void count_deg(const int* __restrict__ dst) {
    int e = blockIdx.x * blockDim.x + threadIdx.x;
    if (e < EE) atomicAdd(&g_cnt[dst[e]], 1);
}
__global__ void calc_dinv() {
    int i = blockIdx.x * blockDim.x + threadIdx.x;
    if (i < NN) g_dinv[i] = rsqrtf((float)g_cnt[i] + 1.0f);   // +1 self loop
}
// single-block exclusive scan -> rowptr, cursor
__global__ void scan_rowptr() {
    __shared__ int s[1024];
    __shared__ int carry;
    const int tid = threadIdx.x;
    if (tid == 0) carry = 0;
    __syncthreads();
    for (int base = 0; base < NN; base += 1024) {
        int i = base + tid;
        int v = (i < NN) ? g_cnt[i] : 0;
        s[tid] = v;
        __syncthreads();
#pragma unroll
        for (int off = 1; off < 1024; off <<= 1) {
            int t = (tid >= off) ? s[tid - off] : 0;
            __syncthreads();
            s[tid] += t;
            __syncthreads();
        }
        if (i < NN) {
            int ex = carry + s[tid] - v;
            g_rowptr[i] = ex;
            g_cursor[i] = ex;
        }
        __syncthreads();
        if (tid == 0) carry += s[1023];
        __syncthreads();
    }
    if (tid == 0) g_rowptr[NN] = carry;
}
__global__ void fill_csr(const int* __restrict__ src, const int* __restrict__ dst) {
    int e = blockIdx.x * blockDim.x + threadIdx.x;
    if (e >= EE) return;
    int s = src[e];
    int d = dst[e];
    int pos = atomicAdd(&g_cursor[d], 1);
    g_eidx[pos] = s;
    g_ew[pos]   = g_dinv[s] * g_dinv[d];
}

// ================= fused propagation step =================
// 10 threads per node; thread q owns channels [4q, 4q+4)
__global__ __launch_bounds__(320)
void prop_step(const float* __restrict__ z,
               float* __restrict__ zn) {
    const int tid  = blockIdx.x * blockDim.x + threadIdx.x;
    const int node = tid / 10;
    const int q    = tid % 10;
    if (node >= NN) return;

    const int beg = g_rowptr[node];
    const int end = g_rowptr[node + 1];

    const float4* __restrict__ z4 = reinterpret_cast<const float4*>(z);

    float4 acc = make_float4(0.f, 0.f, 0.f, 0.f);
    for (int e = beg; e < end; e++) {
        const int   s = __ldg(&g_eidx[e]);
        const float w = __ldg(&g_ew[e]);
        float4 v = __ldg(&z4[(size_t)s * 10 + q]);
        acc.x += w * v.x;
        acc.y += w * v.y;
        acc.z += w * v.z;
        acc.w += w * v.w;
    }

    const float di = g_dinv[node];
    const float sw = di * di;
    const float4 zc = z4[(size_t)node * 10 + q];
    const float4 hh = reinterpret_cast<const float4*>(g_h)[(size_t)node * 10 + q];

    float4 o;
    o.x = (1.0f - ALPHAF) * (acc.x + sw * zc.x) + ALPHAF * hh.x;
    o.y = (1.0f - ALPHAF) * (acc.y + sw * zc.y) + ALPHAF * hh.y;
    o.z = (1.0f - ALPHAF) * (acc.z + sw * zc.z) + ALPHAF * hh.z;
    o.w = (1.0f - ALPHAF) * (acc.w + sw * zc.w) + ALPHAF * hh.w;
    reinterpret_cast<float4*>(zn)[(size_t)node * 10 + q] = o;
}

// ================= launch =================
extern "C" void kernel_launch(void* const* d_in, const int* in_sizes, int n_in,
                              void* d_out, int out_size) {
    const float* x  = (const float*)d_in[0];
    const int*   ei = (const int*)  d_in[1];
    const float* W1 = (const float*)d_in[2];
    const float* b1 = (const float*)d_in[3];
    const float* W2 = (const float*)d_in[4];
    const float* b2 = (const float*)d_in[5];
    float* out = (float*)d_out;

    const int* src = ei;
    const int* dst = ei + EE;

    float *p_h, *p_z0, *p_z1;
    cudaGetSymbolAddress((void**)&p_h,  g_h);
    cudaGetSymbolAddress((void**)&p_z0, g_z0);
    cudaGetSymbolAddress((void**)&p_z1, g_z1);

    // MLP
    dim3 g1(HID / BN, (NN + BM - 1) / BM);
    sgemm1_tc<<<g1, 256>>>(x, W1, b1);
    gemm_relu_2<<<(NN + 7) / 8, dim3(40, 8)>>>(W2, b2);

    // CSR build (by destination)
    zero_cnt <<<(NN + 255) / 256, 256>>>();
    count_deg<<<(EE + 255) / 256, 256>>>(dst);
    calc_dinv<<<(NN + 255) / 256, 256>>>();
    scan_rowptr<<<1, 1024>>>();
    fill_csr <<<(EE + 255) / 256, 256>>>(src, dst);

    // K fused propagation steps (ping-pong)
    const int threads = NN * 10;
    const int blocks  = (threads + 319) / 320;
    for (int it = 0; it < KIT; it++) {
        const float* zcur = (it == 0) ? p_h : ((it & 1) ? p_z1 : p_z0);
        float* znext = (it == KIT - 1) ? out : ((it & 1) ? p_z0 : p_z1);
        prop_step<<<blocks, 320>>>(zcur, znext);
    }
}

// round 6
// speedup vs baseline: 3.3064x; 1.3035x over previous
#include <cuda_runtime.h>
#include <cuda_bf16.h>
#include <cstdint>

#define NN   100000
#define FIN  512
#define HID  256
#define CC   40
#define EE   1600000
#define KIT  10
#define ALPHAF 0.1f

// ---- static device scratch ----
__device__ __align__(128) __nv_bfloat16 g_Xh[(size_t)NN * FIN];
__device__ __align__(128) __nv_bfloat16 g_Xl[(size_t)NN * FIN];
__device__ __align__(128) __nv_bfloat16 g_W1h[FIN * HID];   // [K][N] layout
__device__ __align__(128) __nv_bfloat16 g_W1l[FIN * HID];
__device__ __align__(128) __nv_bfloat16 g_h1h[(size_t)NN * HID];
__device__ __align__(128) __nv_bfloat16 g_h1l[(size_t)NN * HID];
__device__ __align__(128) __nv_bfloat16 g_W2h[HID * CC];    // [K][N]
__device__ __align__(128) __nv_bfloat16 g_W2l[HID * CC];
__device__ float g_h [NN * CC];
__device__ float g_z0[NN * CC];
__device__ float g_z1[NN * CC];
__device__ float g_dinv[NN];
__device__ int   g_cnt[NN];
__device__ int   g_rowptr[NN + 1];
__device__ int   g_cursor[NN];
__device__ int   g_eidx[EE];
__device__ float g_ew  [EE];

// ===================== helpers =====================
__device__ __forceinline__ uint32_t smem_u32(const void* p) {
    return (uint32_t)__cvta_generic_to_shared(p);
}
__device__ __forceinline__ void ldmatrix_x4(uint32_t* r, uint32_t addr) {
    asm volatile("ldmatrix.sync.aligned.m8n8.x4.shared.b16 {%0,%1,%2,%3}, [%4];"
                 : "=r"(r[0]), "=r"(r[1]), "=r"(r[2]), "=r"(r[3]) : "r"(addr));
}
__device__ __forceinline__ void ldmatrix_x2_trans(uint32_t* r, uint32_t addr) {
    asm volatile("ldmatrix.sync.aligned.m8n8.x2.trans.shared.b16 {%0,%1}, [%2];"
                 : "=r"(r[0]), "=r"(r[1]) : "r"(addr));
}
__device__ __forceinline__ void mma_bf16(float* c, const uint32_t* a, const uint32_t* b) {
    asm volatile("mma.sync.aligned.m16n8k16.row.col.f32.bf16.bf16.f32 "
                 "{%0,%1,%2,%3}, {%4,%5,%6,%7}, {%8,%9}, {%0,%1,%2,%3};"
                 : "+f"(c[0]), "+f"(c[1]), "+f"(c[2]), "+f"(c[3])
                 : "r"(a[0]), "r"(a[1]), "r"(a[2]), "r"(a[3]), "r"(b[0]), "r"(b[1]));
}
// truncation split: f = hi(bf16 trunc) + lo(bf16 rn)
__device__ __forceinline__ void split4(float4 v, uint2& hi, uint2& lo) {
    uint32_t b0 = __float_as_uint(v.x), b1 = __float_as_uint(v.y);
    uint32_t b2 = __float_as_uint(v.z), b3 = __float_as_uint(v.w);
    float h0 = __uint_as_float(b0 & 0xFFFF0000u);
    float h1 = __uint_as_float(b1 & 0xFFFF0000u);
    float h2 = __uint_as_float(b2 & 0xFFFF0000u);
    float h3 = __uint_as_float(b3 & 0xFFFF0000u);
    hi.x = __byte_perm(b0, b1, 0x7632);
    hi.y = __byte_perm(b2, b3, 0x7632);
    __nv_bfloat162 p0 = __floats2bfloat162_rn(v.x - h0, v.y - h1);
    __nv_bfloat162 p1 = __floats2bfloat162_rn(v.z - h2, v.w - h3);
    lo.x = *reinterpret_cast<uint32_t*>(&p0);
    lo.y = *reinterpret_cast<uint32_t*>(&p1);
}
__device__ __forceinline__ void store_split2(__nv_bfloat16* hibuf, __nv_bfloat16* lobuf,
                                             size_t idx, float x, float y) {
    uint32_t bx = __float_as_uint(x), by = __float_as_uint(y);
    float hx = __uint_as_float(bx & 0xFFFF0000u);
    float hy = __uint_as_float(by & 0xFFFF0000u);
    reinterpret_cast<uint32_t*>(hibuf)[idx >> 1] = __byte_perm(bx, by, 0x7632);
    __nv_bfloat162 lo = __floats2bfloat162_rn(x - hx, y - hy);
    reinterpret_cast<uint32_t*>(lobuf)[idx >> 1] = *reinterpret_cast<uint32_t*>(&lo);
}

// ===================== one-off split kernels =====================
__global__ void split_x(const float* __restrict__ X) {
    size_t i = (size_t)blockIdx.x * blockDim.x + threadIdx.x;
    if (i >= (size_t)NN * FIN / 4) return;
    float4 v = reinterpret_cast<const float4*>(X)[i];
    uint2 hi, lo;
    split4(v, hi, lo);
    reinterpret_cast<uint2*>(g_Xh)[i] = hi;
    reinterpret_cast<uint2*>(g_Xl)[i] = lo;
}
__global__ void split_w1(const float* __restrict__ W1) {
    int i = blockIdx.x * blockDim.x + threadIdx.x;
    if (i >= FIN * HID / 4) return;
    float4 v = reinterpret_cast<const float4*>(W1)[i];
    uint2 hi, lo;
    split4(v, hi, lo);
    reinterpret_cast<uint2*>(g_W1h)[i] = hi;
    reinterpret_cast<uint2*>(g_W1l)[i] = lo;
}
__global__ void split_w2(const float* __restrict__ W2) {
    int i = blockIdx.x * blockDim.x + threadIdx.x;
    if (i >= HID * CC / 4) return;
    float4 v = reinterpret_cast<const float4*>(W2)[i];
    uint2 hi, lo;
    split4(v, hi, lo);
    reinterpret_cast<uint2*>(g_W2h)[i] = hi;
    reinterpret_cast<uint2*>(g_W2l)[i] = lo;
}

// ===================== GEMM1: h1 = relu(X @ W1 + b1) =====================
#define SA 40
#define SB 136

__global__ __launch_bounds__(256, 1)
void gemm1_tc(const float* __restrict__ bias) {
    __shared__ __align__(16) __nv_bfloat16 Ah[128 * SA];
    __shared__ __align__(16) __nv_bfloat16 Al[128 * SA];
    __shared__ __align__(16) __nv_bfloat16 Bh[32 * SB];
    __shared__ __align__(16) __nv_bfloat16 Bl[32 * SB];

    const int tid  = threadIdx.x;
    const int lane = tid & 31;
    const int warp = tid >> 5;
    const int wm   = warp >> 2;
    const int wn   = warp & 3;
    const int bm   = blockIdx.y * 128;
    const int bn   = blockIdx.x * 128;

    const int xrow = tid >> 1;
    const int xks  = (tid & 1) * 16;
    const int wk   = tid >> 3;
    const int wn0  = (tid & 7) * 16;
    const bool xok = (bm + xrow) < NN;

    const __nv_bfloat16* xh = g_Xh + (size_t)(bm + xrow) * FIN + xks;
    const __nv_bfloat16* xl = g_Xl + (size_t)(bm + xrow) * FIN + xks;
    const __nv_bfloat16* wh = g_W1h + (size_t)wk * HID + bn + wn0;
    const __nv_bfloat16* wl = g_W1l + (size_t)wk * HID + bn + wn0;

    const uint4 zz = make_uint4(0, 0, 0, 0);
    uint4 rxh[2], rxl[2], rwh[2], rwl[2];
#pragma unroll
    for (int j = 0; j < 2; j++) {
        rxh[j] = xok ? *reinterpret_cast<const uint4*>(xh + j * 8) : zz;
        rxl[j] = xok ? *reinterpret_cast<const uint4*>(xl + j * 8) : zz;
        rwh[j] = *reinterpret_cast<const uint4*>(wh + j * 8);
        rwl[j] = *reinterpret_cast<const uint4*>(wl + j * 8);
    }

    float acc[4][4][4];
#pragma unroll
    for (int i = 0; i < 4; i++)
#pragma unroll
        for (int j = 0; j < 4; j++)
#pragma unroll
            for (int k = 0; k < 4; k++) acc[i][j][k] = 0.f;

    const int agrp   = lane >> 3;
    const int arow_l = (agrp & 1) * 8 + (lane & 7);
    const int akcol  = (agrp >> 1) * 8;
    const int bkrow  = lane & 15;

    for (int kt = 0; kt < FIN / 32; kt++) {
        *reinterpret_cast<uint4*>(&Ah[xrow * SA + xks])     = rxh[0];
        *reinterpret_cast<uint4*>(&Ah[xrow * SA + xks + 8]) = rxh[1];
        *reinterpret_cast<uint4*>(&Al[xrow * SA + xks])     = rxl[0];
        *reinterpret_cast<uint4*>(&Al[xrow * SA + xks + 8]) = rxl[1];
        *reinterpret_cast<uint4*>(&Bh[wk * SB + wn0])       = rwh[0];
        *reinterpret_cast<uint4*>(&Bh[wk * SB + wn0 + 8])   = rwh[1];
        *reinterpret_cast<uint4*>(&Bl[wk * SB + wn0])       = rwl[0];
        *reinterpret_cast<uint4*>(&Bl[wk * SB + wn0 + 8])   = rwl[1];
        __syncthreads();

        if (kt + 1 < FIN / 32) {
            const int ko = (kt + 1) * 32;
#pragma unroll
            for (int j = 0; j < 2; j++) {
                rxh[j] = xok ? *reinterpret_cast<const uint4*>(xh + ko + j * 8) : zz;
                rxl[j] = xok ? *reinterpret_cast<const uint4*>(xl + ko + j * 8) : zz;
                rwh[j] = *reinterpret_cast<const uint4*>(wh + (size_t)ko * HID + j * 8);
                rwl[j] = *reinterpret_cast<const uint4*>(wl + (size_t)ko * HID + j * 8);
            }
        }

#pragma unroll
        for (int ks = 0; ks < 32; ks += 16) {
            uint32_t a_h[4][4], a_l[4][4], b_h[4][2], b_l[4][2];
#pragma unroll
            for (int im = 0; im < 4; im++) {
                int mrow = wm * 64 + im * 16 + arow_l;
                ldmatrix_x4(a_h[im], smem_u32(&Ah[mrow * SA + ks + akcol]));
                ldmatrix_x4(a_l[im], smem_u32(&Al[mrow * SA + ks + akcol]));
            }
#pragma unroll
            for (int in_ = 0; in_ < 4; in_++) {
                int ncol = wn * 32 + in_ * 8;
                ldmatrix_x2_trans(b_h[in_], smem_u32(&Bh[(ks + bkrow) * SB + ncol]));
                ldmatrix_x2_trans(b_l[in_], smem_u32(&Bl[(ks + bkrow) * SB + ncol]));
            }
#pragma unroll
            for (int im = 0; im < 4; im++)
#pragma unroll
                for (int in_ = 0; in_ < 4; in_++) {
                    mma_bf16(acc[im][in_], a_h[im], b_h[in_]);
                    mma_bf16(acc[im][in_], a_h[im], b_l[in_]);
                    mma_bf16(acc[im][in_], a_l[im], b_h[in_]);
                }
        }
        __syncthreads();
    }

    // epilogue: bias + relu, write h1 as split bf16
    const int r_in = lane >> 2;
    const int c_in = (lane & 3) * 2;
#pragma unroll
    for (int in_ = 0; in_ < 4; in_++) {
        int col = bn + wn * 32 + in_ * 8 + c_in;
        float b0 = bias[col], b1 = bias[col + 1];
#pragma unroll
        for (int im = 0; im < 4; im++) {
            int row0 = bm + wm * 64 + im * 16 + r_in;
            if (row0 < NN) {
                float ox = fmaxf(acc[im][in_][0] + b0, 0.f);
                float oy = fmaxf(acc[im][in_][1] + b1, 0.f);
                store_split2(g_h1h, g_h1l, (size_t)row0 * HID + col, ox, oy);
            }
            int row1 = row0 + 8;
            if (row1 < NN) {
                float ox = fmaxf(acc[im][in_][2] + b0, 0.f);
                float oy = fmaxf(acc[im][in_][3] + b1, 0.f);
                store_split2(g_h1h, g_h1l, (size_t)row1 * HID + col, ox, oy);
            }
        }
    }
}

// ===================== GEMM2: h = relu(h1 @ W2 + b2) on tensor cores =====================
#define SB2 48
#define SA2 72
#define G2_SMEM ((HID * SB2 * 2 + 128 * SA2 * 2) * 2)   // bytes: W2 h/l + A h/l

__global__ __launch_bounds__(256, 2)
void gemm2_tc(const float* __restrict__ b2) {
    extern __shared__ __align__(16) char sm2[];
    __nv_bfloat16* W2hs = reinterpret_cast<__nv_bfloat16*>(sm2);
    __nv_bfloat16* W2ls = W2hs + HID * SB2;
    __nv_bfloat16* A2h  = W2ls + HID * SB2;
    __nv_bfloat16* A2l  = A2h + 128 * SA2;

    const int tid  = threadIdx.x;
    const int lane = tid & 31;
    const int warp = tid >> 5;          // 0..7, 16 rows each
    const int bm   = blockIdx.x * 128;

    for (int i = tid; i < HID * CC; i += 256) {
        int k = i / CC, n = i % CC;
        W2hs[k * SB2 + n] = g_W2h[i];
        W2ls[k * SB2 + n] = g_W2l[i];
    }

    float acc[5][4];
#pragma unroll
    for (int n = 0; n < 5; n++)
#pragma unroll
        for (int j = 0; j < 4; j++) acc[n][j] = 0.f;

    const int agrp   = lane >> 3;
    const int arow_l = (agrp & 1) * 8 + (lane & 7);
    const int akcol  = (agrp >> 1) * 8;
    const int bkrow  = lane & 15;

    const int arow  = tid >> 1;
    const int apart = (tid & 1) * 32;
    const bool aok  = (bm + arow) < NN;
    const uint4 zz  = make_uint4(0, 0, 0, 0);

    for (int kc = 0; kc < 4; kc++) {
        // stage A chunk [128][64]
#pragma unroll
        for (int j = 0; j < 4; j++) {
            size_t gidx = (size_t)(bm + arow) * HID + kc * 64 + apart + j * 8;
            uint4 vh = aok ? *reinterpret_cast<const uint4*>(&g_h1h[gidx]) : zz;
            uint4 vl = aok ? *reinterpret_cast<const uint4*>(&g_h1l[gidx]) : zz;
            *reinterpret_cast<uint4*>(&A2h[arow * SA2 + apart + j * 8]) = vh;
            *reinterpret_cast<uint4*>(&A2l[arow * SA2 + apart + j * 8]) = vl;
        }
        __syncthreads();

#pragma unroll
        for (int ks = 0; ks < 64; ks += 16) {
            uint32_t a_h[4], a_l[4];
            ldmatrix_x4(a_h, smem_u32(&A2h[(warp * 16 + arow_l) * SA2 + ks + akcol]));
            ldmatrix_x4(a_l, smem_u32(&A2l[(warp * 16 + arow_l) * SA2 + ks + akcol]));
#pragma unroll
            for (int n = 0; n < 5; n++) {
                uint32_t b_h[2], b_l[2];
                ldmatrix_x2_trans(b_h, smem_u32(&W2hs[(kc * 64 + ks + bkrow) * SB2 + n * 8]));
                ldmatrix_x2_trans(b_l, smem_u32(&W2ls[(kc * 64 + ks + bkrow) * SB2 + n * 8]));
                mma_bf16(acc[n], a_h, b_h);
                mma_bf16(acc[n], a_h, b_l);
                mma_bf16(acc[n], a_l, b_h);
            }
        }
        __syncthreads();
    }

    const int r_in = lane >> 2;
    const int c_in = (lane & 3) * 2;
    const int row0 = bm + warp * 16 + r_in;
    const int row1 = row0 + 8;
#pragma unroll
    for (int n = 0; n < 5; n++) {
        int col = n * 8 + c_in;
        float bb0 = b2[col], bb1 = b2[col + 1];
        if (row0 < NN) {
            float2 o;
            o.x = fmaxf(acc[n][0] + bb0, 0.f);
            o.y = fmaxf(acc[n][1] + bb1, 0.f);
            *reinterpret_cast<float2*>(&g_h[(size_t)row0 * CC + col]) = o;
        }
        if (row1 < NN) {
            float2 o;
            o.x = fmaxf(acc[n][2] + bb0, 0.f);
            o.y = fmaxf(acc[n][3] + bb1, 0.f);
            *reinterpret_cast<float2*>(&g_h[(size_t)row1 * CC + col]) = o;
        }
    }
}

// ================= degree / CSR build =================
__global__ void zero_cnt() {
    int i = blockIdx.x * blockDim.x + threadIdx.x;
    if (i < NN) g_cnt[i] = 0;
}
__global__ void count_deg(const int* __restrict__ dst) {
    int e = blockIdx.x * blockDim.x + threadIdx.x;
    if (e < EE) atomicAdd(&g_cnt[dst[e]], 1);
}
__global__ void calc_dinv() {
    int i = blockIdx.x * blockDim.x + threadIdx.x;
    if (i < NN) g_dinv[i] = rsqrtf((float)g_cnt[i] + 1.0f);
}
__global__ void scan_rowptr() {
    __shared__ int s[1024];
    __shared__ int carry;
    const int tid = threadIdx.x;
    if (tid == 0) carry = 0;
    __syncthreads();
    for (int base = 0; base < NN; base += 1024) {
        int i = base + tid;
        int v = (i < NN) ? g_cnt[i] : 0;
        s[tid] = v;
        __syncthreads();
#pragma unroll
        for (int off = 1; off < 1024; off <<= 1) {
            int t = (tid >= off) ? s[tid - off] : 0;
            __syncthreads();
            s[tid] += t;
            __syncthreads();
        }
        if (i < NN) {
            int ex = carry + s[tid] - v;
            g_rowptr[i] = ex;
            g_cursor[i] = ex;
        }
        __syncthreads();
        if (tid == 0) carry += s[1023];
        __syncthreads();
    }
    if (tid == 0) g_rowptr[NN] = carry;
}
__global__ void fill_csr(const int* __restrict__ src, const int* __restrict__ dst) {
    int e = blockIdx.x * blockDim.x + threadIdx.x;
    if (e >= EE) return;
    int s = src[e];
    int d = dst[e];
    int pos = atomicAdd(&g_cursor[d], 1);
    g_eidx[pos] = s;
    g_ew[pos]   = g_dinv[s] * g_dinv[d];
}

// ================= fused propagation step =================
__global__ __launch_bounds__(320)
void prop_step(const float* __restrict__ z,
               float* __restrict__ zn) {
    const int tid  = blockIdx.x * blockDim.x + threadIdx.x;
    const int node = tid / 10;
    const int q    = tid % 10;
    if (node >= NN) return;

    const int beg = g_rowptr[node];
    const int end = g_rowptr[node + 1];

    const float4* __restrict__ z4 = reinterpret_cast<const float4*>(z);

    float4 acc = make_float4(0.f, 0.f, 0.f, 0.f);
    for (int e = beg; e < end; e++) {
        const int   s = __ldg(&g_eidx[e]);
        const float w = __ldg(&g_ew[e]);
        float4 v = __ldg(&z4[(size_t)s * 10 + q]);
        acc.x += w * v.x;
        acc.y += w * v.y;
        acc.z += w * v.z;
        acc.w += w * v.w;
    }

    const float di = g_dinv[node];
    const float sw = di * di;
    const float4 zc = z4[(size_t)node * 10 + q];
    const float4 hh = reinterpret_cast<const float4*>(g_h)[(size_t)node * 10 + q];

    float4 o;
    o.x = (1.0f - ALPHAF) * (acc.x + sw * zc.x) + ALPHAF * hh.x;
    o.y = (1.0f - ALPHAF) * (acc.y + sw * zc.y) + ALPHAF * hh.y;
    o.z = (1.0f - ALPHAF) * (acc.z + sw * zc.z) + ALPHAF * hh.z;
    o.w = (1.0f - ALPHAF) * (acc.w + sw * zc.w) + ALPHAF * hh.w;
    reinterpret_cast<float4*>(zn)[(size_t)node * 10 + q] = o;
}

// ================= launch =================
extern "C" void kernel_launch(void* const* d_in, const int* in_sizes, int n_in,
                              void* d_out, int out_size) {
    const float* x  = (const float*)d_in[0];
    const int*   ei = (const int*)  d_in[1];
    const float* W1 = (const float*)d_in[2];
    const float* b1 = (const float*)d_in[3];
    const float* W2 = (const float*)d_in[4];
    const float* b2 = (const float*)d_in[5];
    float* out = (float*)d_out;

    const int* src = ei;
    const int* dst = ei + EE;

    float *p_h, *p_z0, *p_z1;
    cudaGetSymbolAddress((void**)&p_h,  g_h);
    cudaGetSymbolAddress((void**)&p_z0, g_z0);
    cudaGetSymbolAddress((void**)&p_z1, g_z1);

    // splits
    split_x <<<(int)(((size_t)NN * FIN / 4 + 255) / 256), 256>>>(x);
    split_w1<<<(FIN * HID / 4 + 255) / 256, 256>>>(W1);
    split_w2<<<(HID * CC / 4 + 255) / 256, 256>>>(W2);

    // MLP on tensor cores
    dim3 g1(HID / 128, (NN + 127) / 128);
    gemm1_tc<<<g1, 256>>>(b1);
    cudaFuncSetAttribute(gemm2_tc, cudaFuncAttributeMaxDynamicSharedMemorySize, G2_SMEM);
    gemm2_tc<<<(NN + 127) / 128, 256, G2_SMEM>>>(b2);

    // CSR build (by destination)
    zero_cnt <<<(NN + 255) / 256, 256>>>();
    count_deg<<<(EE + 255) / 256, 256>>>(dst);
    calc_dinv<<<(NN + 255) / 256, 256>>>();
    scan_rowptr<<<1, 1024>>>();
    fill_csr <<<(EE + 255) / 256, 256>>>(src, dst);

    // K fused propagation steps (ping-pong)
    const int threads = NN * 10;
    const int blocks  = (threads + 319) / 320;
    for (int it = 0; it < KIT; it++) {
        const float* zcur = (it == 0) ? p_h : ((it & 1) ? p_z1 : p_z0);
        float* znext = (it == KIT - 1) ? out : ((it & 1) ? p_z0 : p_z1);
        prop_step<<<blocks, 320>>>(zcur, znext);
    }
}

// round 7
// speedup vs baseline: 3.5412x; 1.0710x over previous
#include <cuda_runtime.h>
#include <cuda_bf16.h>
#include <cstdint>

#define NN   100000
#define FIN  512
#define HID  256
#define CC   40
#define EE   1600000
#define KIT  10
#define ALPHAF 0.1f

// ---- static device scratch ----
__device__ __align__(128) __nv_bfloat16 g_Xh[(size_t)NN * FIN];
__device__ __align__(128) __nv_bfloat16 g_Xl[(size_t)NN * FIN];
__device__ __align__(128) __nv_bfloat16 g_W1h[FIN * HID];   // [K][N]
__device__ __align__(128) __nv_bfloat16 g_W1l[FIN * HID];
__device__ __align__(128) __nv_bfloat16 g_h1h[(size_t)NN * HID];
__device__ __align__(128) __nv_bfloat16 g_h1l[(size_t)NN * HID];
__device__ __align__(128) __nv_bfloat16 g_W2h[HID * CC];    // [K][N]
__device__ __align__(128) __nv_bfloat16 g_W2l[HID * CC];
__device__ float g_h [NN * CC];
__device__ float g_z0[NN * CC];
__device__ float g_z1[NN * CC];
__device__ float g_dinv[NN];
__device__ int   g_cnt[NN];
__device__ int   g_rowptr[NN + 1];
__device__ int   g_cursor[NN];
__device__ int   g_eidx[EE];
__device__ float g_ew  [EE];

// ===================== helpers =====================
__device__ __forceinline__ uint32_t smem_u32(const void* p) {
    return (uint32_t)__cvta_generic_to_shared(p);
}
__device__ __forceinline__ void ldmatrix_x4(uint32_t* r, uint32_t addr) {
    asm volatile("ldmatrix.sync.aligned.m8n8.x4.shared.b16 {%0,%1,%2,%3}, [%4];"
                 : "=r"(r[0]), "=r"(r[1]), "=r"(r[2]), "=r"(r[3]) : "r"(addr));
}
__device__ __forceinline__ void ldmatrix_x4_trans(uint32_t* r, uint32_t addr) {
    asm volatile("ldmatrix.sync.aligned.m8n8.x4.trans.shared.b16 {%0,%1,%2,%3}, [%4];"
                 : "=r"(r[0]), "=r"(r[1]), "=r"(r[2]), "=r"(r[3]) : "r"(addr));
}
__device__ __forceinline__ void mma_bf16(float* c, const uint32_t* a, const uint32_t* b) {
    asm volatile("mma.sync.aligned.m16n8k16.row.col.f32.bf16.bf16.f32 "
                 "{%0,%1,%2,%3}, {%4,%5,%6,%7}, {%8,%9}, {%0,%1,%2,%3};"
                 : "+f"(c[0]), "+f"(c[1]), "+f"(c[2]), "+f"(c[3])
                 : "r"(a[0]), "r"(a[1]), "r"(a[2]), "r"(a[3]), "r"(b[0]), "r"(b[1]));
}
__device__ __forceinline__ void cp16z(uint32_t dst, const void* src, uint32_t sz) {
    asm volatile("cp.async.cg.shared.global [%0], [%1], 16, %2;"
                 :: "r"(dst), "l"(src), "r"(sz));
}
__device__ __forceinline__ void cp_commit() {
    asm volatile("cp.async.commit_group;");
}
// truncation split: f = hi(bf16 trunc) + lo(bf16 rn)
__device__ __forceinline__ void split4(float4 v, uint2& hi, uint2& lo) {
    uint32_t b0 = __float_as_uint(v.x), b1 = __float_as_uint(v.y);
    uint32_t b2 = __float_as_uint(v.z), b3 = __float_as_uint(v.w);
    float h0 = __uint_as_float(b0 & 0xFFFF0000u);
    float h1 = __uint_as_float(b1 & 0xFFFF0000u);
    float h2 = __uint_as_float(b2 & 0xFFFF0000u);
    float h3 = __uint_as_float(b3 & 0xFFFF0000u);
    hi.x = __byte_perm(b0, b1, 0x7632);
    hi.y = __byte_perm(b2, b3, 0x7632);
    __nv_bfloat162 p0 = __floats2bfloat162_rn(v.x - h0, v.y - h1);
    __nv_bfloat162 p1 = __floats2bfloat162_rn(v.z - h2, v.w - h3);
    lo.x = *reinterpret_cast<uint32_t*>(&p0);
    lo.y = *reinterpret_cast<uint32_t*>(&p1);
}
__device__ __forceinline__ void store_split2(__nv_bfloat16* hibuf, __nv_bfloat16* lobuf,
                                             size_t idx, float x, float y) {
    uint32_t bx = __float_as_uint(x), by = __float_as_uint(y);
    float hx = __uint_as_float(bx & 0xFFFF0000u);
    float hy = __uint_as_float(by & 0xFFFF0000u);
    reinterpret_cast<uint32_t*>(hibuf)[idx >> 1] = __byte_perm(bx, by, 0x7632);
    __nv_bfloat162 lo = __floats2bfloat162_rn(x - hx, y - hy);
    reinterpret_cast<uint32_t*>(lobuf)[idx >> 1] = *reinterpret_cast<uint32_t*>(&lo);
}

// ===================== one-off split kernels =====================
__global__ void split_x(const float* __restrict__ X) {
    size_t i = (size_t)blockIdx.x * blockDim.x + threadIdx.x;
    if (i >= (size_t)NN * FIN / 4) return;
    float4 v = reinterpret_cast<const float4*>(X)[i];
    uint2 hi, lo;
    split4(v, hi, lo);
    reinterpret_cast<uint2*>(g_Xh)[i] = hi;
    reinterpret_cast<uint2*>(g_Xl)[i] = lo;
}
__global__ void split_w1(const float* __restrict__ W1) {
    int i = blockIdx.x * blockDim.x + threadIdx.x;
    if (i >= FIN * HID / 4) return;
    float4 v = reinterpret_cast<const float4*>(W1)[i];
    uint2 hi, lo;
    split4(v, hi, lo);
    reinterpret_cast<uint2*>(g_W1h)[i] = hi;
    reinterpret_cast<uint2*>(g_W1l)[i] = lo;
}
__global__ void split_w2(const float* __restrict__ W2) {
    int i = blockIdx.x * blockDim.x + threadIdx.x;
    if (i >= HID * CC / 4) return;
    float4 v = reinterpret_cast<const float4*>(W2)[i];
    uint2 hi, lo;
    split4(v, hi, lo);
    reinterpret_cast<uint2*>(g_W2h)[i] = hi;
    reinterpret_cast<uint2*>(g_W2l)[i] = lo;
}

// ===================== GEMM1: h1 = relu(X @ W1 + b1) =====================
// double-buffered cp.async, 2 CTAs/SM, merged hi/lo B ldmatrix
#define SA 40
#define SB 136
#define A_BUF (128 * SA * 2)          // 10240 B
#define B_BUF (32 * SB * 2)           // 8704 B
#define ST1   (2 * A_BUF + 2 * B_BUF) // 37888 B per stage
#define G1_SMEM (2 * ST1)             // 75776 B
#define NKT (FIN / 32)                // 16

__global__ __launch_bounds__(256, 2)
void gemm1_tc(const float* __restrict__ bias) {
    extern __shared__ __align__(16) char sm1[];

    const int tid  = threadIdx.x;
    const int lane = tid & 31;
    const int warp = tid >> 5;
    const int wm   = warp >> 2;
    const int wn   = warp & 3;
    const int bm   = blockIdx.y * 128;
    const int bn   = blockIdx.x * 128;

    // cp.async mapping
    const int arow = tid >> 1;
    const int akp  = (tid & 1) * 16;
    const int brow = tid >> 3;
    const int bcol = (tid & 7) * 16;
    const uint32_t xsz = ((bm + arow) < NN) ? 16u : 0u;

    const __nv_bfloat16* srcAh = g_Xh + (size_t)(bm + arow) * FIN + akp;
    const __nv_bfloat16* srcAl = g_Xl + (size_t)(bm + arow) * FIN + akp;
    const __nv_bfloat16* srcBh = g_W1h + (size_t)brow * HID + bn + bcol;
    const __nv_bfloat16* srcBl = g_W1l + (size_t)brow * HID + bn + bcol;

    const uint32_t smb = smem_u32(sm1);
    const uint32_t dAh = smb + arow * (SA * 2) + akp * 2;
    const uint32_t dAl = dAh + A_BUF;
    const uint32_t dBh = smb + 2 * A_BUF + brow * (SB * 2) + bcol * 2;
    const uint32_t dBl = dBh + B_BUF;

    auto load_stage = [&](int kt, int s) {
        const uint32_t so = (uint32_t)s * ST1;
        const int ko = kt * 32;
        cp16z(dAh + so,      srcAh + ko,     xsz);
        cp16z(dAh + so + 16, srcAh + ko + 8, xsz);
        cp16z(dAl + so,      srcAl + ko,     xsz);
        cp16z(dAl + so + 16, srcAl + ko + 8, xsz);
        cp16z(dBh + so,      srcBh + (size_t)ko * HID,     16u);
        cp16z(dBh + so + 16, srcBh + (size_t)ko * HID + 8, 16u);
        cp16z(dBl + so,      srcBl + (size_t)ko * HID,     16u);
        cp16z(dBl + so + 16, srcBl + (size_t)ko * HID + 8, 16u);
        cp_commit();
    };

    float acc[4][4][4];
#pragma unroll
    for (int i = 0; i < 4; i++)
#pragma unroll
        for (int j = 0; j < 4; j++)
#pragma unroll
            for (int k = 0; k < 4; k++) acc[i][j][k] = 0.f;

    const int agrp   = lane >> 3;
    const int arow_l = (agrp & 1) * 8 + (lane & 7);
    const int akcol  = (agrp >> 1) * 8;
    // merged-B ldmatrix: lanes 0-15 read Bh rows, lanes 16-31 read Bl rows
    const int bkrow  = lane & 15;
    const uint32_t bsel = (lane < 16) ? 0u : (uint32_t)B_BUF;

    load_stage(0, 0);

    for (int kt = 0; kt < NKT; kt++) {
        const int s = kt & 1;
        const uint32_t so = (uint32_t)s * ST1;

        if (kt + 1 < NKT) {
            load_stage(kt + 1, s ^ 1);
            asm volatile("cp.async.wait_group 1;");
        } else {
            asm volatile("cp.async.wait_group 0;");
        }
        __syncthreads();

#pragma unroll
        for (int ks = 0; ks < 32; ks += 16) {
            uint32_t a_h[4][4], a_l[4][4];
#pragma unroll
            for (int im = 0; im < 4; im++) {
                int mrow = wm * 64 + im * 16 + arow_l;
                uint32_t abase = smb + so + mrow * (SA * 2) + (ks + akcol) * 2;
                ldmatrix_x4(a_h[im], abase);
                ldmatrix_x4(a_l[im], abase + A_BUF);
            }
#pragma unroll
            for (int in_ = 0; in_ < 4; in_++) {
                int ncol = wn * 32 + in_ * 8;
                uint32_t bb[4];
                uint32_t baddr = smb + so + 2 * A_BUF + bsel
                               + (ks + bkrow) * (SB * 2) + ncol * 2;
                ldmatrix_x4_trans(bb, baddr);   // bb[0..1]=Bh, bb[2..3]=Bl
#pragma unroll
                for (int im = 0; im < 4; im++) {
                    mma_bf16(acc[im][in_], a_h[im], &bb[0]);
                    mma_bf16(acc[im][in_], a_h[im], &bb[2]);
                    mma_bf16(acc[im][in_], a_l[im], &bb[0]);
                }
            }
        }
        __syncthreads();
    }

    // epilogue: bias + relu, write h1 as split bf16
    const int r_in = lane >> 2;
    const int c_in = (lane & 3) * 2;
#pragma unroll
    for (int in_ = 0; in_ < 4; in_++) {
        int col = bn + wn * 32 + in_ * 8 + c_in;
        float b0 = bias[col], b1 = bias[col + 1];
#pragma unroll
        for (int im = 0; im < 4; im++) {
            int row0 = bm + wm * 64 + im * 16 + r_in;
            if (row0 < NN) {
                float ox = fmaxf(acc[im][in_][0] + b0, 0.f);
                float oy = fmaxf(acc[im][in_][1] + b1, 0.f);
                store_split2(g_h1h, g_h1l, (size_t)row0 * HID + col, ox, oy);
            }
            int row1 = row0 + 8;
            if (row1 < NN) {
                float ox = fmaxf(acc[im][in_][2] + b0, 0.f);
                float oy = fmaxf(acc[im][in_][3] + b1, 0.f);
                store_split2(g_h1h, g_h1l, (size_t)row1 * HID + col, ox, oy);
            }
        }
    }
}

// ===================== GEMM2: h = relu(h1 @ W2 + b2) =====================
#define SB2 48
#define SA2 72
#define G2_SMEM ((HID * SB2 * 2 + 128 * SA2 * 2) * 2)

__global__ __launch_bounds__(256, 2)
void gemm2_tc(const float* __restrict__ b2) {
    extern __shared__ __align__(16) char sm2[];
    __nv_bfloat16* W2hs = reinterpret_cast<__nv_bfloat16*>(sm2);
    __nv_bfloat16* W2ls = W2hs + HID * SB2;
    __nv_bfloat16* A2h  = W2ls + HID * SB2;
    __nv_bfloat16* A2l  = A2h + 128 * SA2;

    const int tid  = threadIdx.x;
    const int lane = tid & 31;
    const int warp = tid >> 5;
    const int bm   = blockIdx.x * 128;

    for (int i = tid; i < HID * CC; i += 256) {
        int k = i / CC, n = i % CC;
        W2hs[k * SB2 + n] = g_W2h[i];
        W2ls[k * SB2 + n] = g_W2l[i];
    }

    float acc[5][4];
#pragma unroll
    for (int n = 0; n < 5; n++)
#pragma unroll
        for (int j = 0; j < 4; j++) acc[n][j] = 0.f;

    const int agrp   = lane >> 3;
    const int arow_l = (agrp & 1) * 8 + (lane & 7);
    const int akcol  = (agrp >> 1) * 8;
    const int bkrow  = lane & 15;
    const int bsel   = (lane < 16) ? 0 : HID * SB2;   // Bh vs Bl (elements)

    const int arow  = tid >> 1;
    const int apart = (tid & 1) * 32;
    const bool aok  = (bm + arow) < NN;
    const uint4 zz  = make_uint4(0, 0, 0, 0);

    for (int kc = 0; kc < 4; kc++) {
#pragma unroll
        for (int j = 0; j < 4; j++) {
            size_t gidx = (size_t)(bm + arow) * HID + kc * 64 + apart + j * 8;
            uint4 vh = aok ? *reinterpret_cast<const uint4*>(&g_h1h[gidx]) : zz;
            uint4 vl = aok ? *reinterpret_cast<const uint4*>(&g_h1l[gidx]) : zz;
            *reinterpret_cast<uint4*>(&A2h[arow * SA2 + apart + j * 8]) = vh;
            *reinterpret_cast<uint4*>(&A2l[arow * SA2 + apart + j * 8]) = vl;
        }
        __syncthreads();

#pragma unroll
        for (int ks = 0; ks < 64; ks += 16) {
            uint32_t a_h[4], a_l[4];
            ldmatrix_x4(a_h, smem_u32(&A2h[(warp * 16 + arow_l) * SA2 + ks + akcol]));
            ldmatrix_x4(a_l, smem_u32(&A2l[(warp * 16 + arow_l) * SA2 + ks + akcol]));
#pragma unroll
            for (int n = 0; n < 5; n++) {
                uint32_t bb[4];
                ldmatrix_x4_trans(bb, smem_u32(&W2hs[bsel + (kc * 64 + ks + bkrow) * SB2 + n * 8]));
                mma_bf16(acc[n], a_h, &bb[0]);
                mma_bf16(acc[n], a_h, &bb[2]);
                mma_bf16(acc[n], a_l, &bb[0]);
            }
        }
        __syncthreads();
    }

    const int r_in = lane >> 2;
    const int c_in = (lane & 3) * 2;
    const int row0 = bm + warp * 16 + r_in;
    const int row1 = row0 + 8;
#pragma unroll
    for (int n = 0; n < 5; n++) {
        int col = n * 8 + c_in;
        float bb0 = b2[col], bb1 = b2[col + 1];
        if (row0 < NN) {
            float2 o;
            o.x = fmaxf(acc[n][0] + bb0, 0.f);
            o.y = fmaxf(acc[n][1] + bb1, 0.f);
            *reinterpret_cast<float2*>(&g_h[(size_t)row0 * CC + col]) = o;
        }
        if (row1 < NN) {
            float2 o;
            o.x = fmaxf(acc[n][2] + bb0, 0.f);
            o.y = fmaxf(acc[n][3] + bb1, 0.f);
            *reinterpret_cast<float2*>(&g_h[(size_t)row1 * CC + col]) = o;
        }
    }
}

// ================= degree / CSR build =================
__global__ void zero_cnt() {
    int i = blockIdx.x * blockDim.x + threadIdx.x;
    if (i < NN) g_cnt[i] = 0;
}
__global__ void count_deg(const int* __restrict__ dst) {
    int e = blockIdx.x * blockDim.x + threadIdx.x;
    if (e < EE) atomicAdd(&g_cnt[dst[e]], 1);
}
__global__ void calc_dinv() {
    int i = blockIdx.x * blockDim.x + threadIdx.x;
    if (i < NN) g_dinv[i] = rsqrtf((float)g_cnt[i] + 1.0f);
}
__global__ void scan_rowptr() {
    __shared__ int s[1024];
    __shared__ int carry;
    const int tid = threadIdx.x;
    if (tid == 0) carry = 0;
    __syncthreads();
    for (int base = 0; base < NN; base += 1024) {
        int i = base + tid;
        int v = (i < NN) ? g_cnt[i] : 0;
        s[tid] = v;
        __syncthreads();
#pragma unroll
        for (int off = 1; off < 1024; off <<= 1) {
            int t = (tid >= off) ? s[tid - off] : 0;
            __syncthreads();
            s[tid] += t;
            __syncthreads();
        }
        if (i < NN) {
            int ex = carry + s[tid] - v;
            g_rowptr[i] = ex;
            g_cursor[i] = ex;
        }
        __syncthreads();
        if (tid == 0) carry += s[1023];
        __syncthreads();
    }
    if (tid == 0) g_rowptr[NN] = carry;
}
__global__ void fill_csr(const int* __restrict__ src, const int* __restrict__ dst) {
    int e = blockIdx.x * blockDim.x + threadIdx.x;
    if (e >= EE) return;
    int s = src[e];
    int d = dst[e];
    int pos = atomicAdd(&g_cursor[d], 1);
    g_eidx[pos] = s;
    g_ew[pos]   = g_dinv[s] * g_dinv[d];
}

// ================= fused propagation step =================
__global__ __launch_bounds__(320)
void prop_step(const float* __restrict__ z,
               float* __restrict__ zn) {
    const int tid  = blockIdx.x * blockDim.x + threadIdx.x;
    const int node = tid / 10;
    const int q    = tid % 10;
    if (node >= NN) return;

    const int beg = g_rowptr[node];
    const int end = g_rowptr[node + 1];

    const float4* __restrict__ z4 = reinterpret_cast<const float4*>(z);

    float4 acc = make_float4(0.f, 0.f, 0.f, 0.f);
#pragma unroll 2
    for (int e = beg; e < end; e++) {
        const int   s = __ldg(&g_eidx[e]);
        const float w = __ldg(&g_ew[e]);
        float4 v = __ldg(&z4[(size_t)s * 10 + q]);
        acc.x += w * v.x;
        acc.y += w * v.y;
        acc.z += w * v.z;
        acc.w += w * v.w;
    }

    const float di = g_dinv[node];
    const float sw = di * di;
    const float4 zc = z4[(size_t)node * 10 + q];
    const float4 hh = reinterpret_cast<const float4*>(g_h)[(size_t)node * 10 + q];

    float4 o;
    o.x = (1.0f - ALPHAF) * (acc.x + sw * zc.x) + ALPHAF * hh.x;
    o.y = (1.0f - ALPHAF) * (acc.y + sw * zc.y) + ALPHAF * hh.y;
    o.z = (1.0f - ALPHAF) * (acc.z + sw * zc.z) + ALPHAF * hh.z;
    o.w = (1.0f - ALPHAF) * (acc.w + sw * zc.w) + ALPHAF * hh.w;
    reinterpret_cast<float4*>(zn)[(size_t)node * 10 + q] = o;
}

// ================= launch =================
extern "C" void kernel_launch(void* const* d_in, const int* in_sizes, int n_in,
                              void* d_out, int out_size) {
    const float* x  = (const float*)d_in[0];
    const int*   ei = (const int*)  d_in[1];
    const float* W1 = (const float*)d_in[2];
    const float* b1 = (const float*)d_in[3];
    const float* W2 = (const float*)d_in[4];
    const float* b2 = (const float*)d_in[5];
    float* out = (float*)d_out;

    const int* src = ei;
    const int* dst = ei + EE;

    float *p_h, *p_z0, *p_z1;
    cudaGetSymbolAddress((void**)&p_h,  g_h);
    cudaGetSymbolAddress((void**)&p_z0, g_z0);
    cudaGetSymbolAddress((void**)&p_z1, g_z1);

    // splits
    split_x <<<(int)(((size_t)NN * FIN / 4 + 255) / 256), 256>>>(x);
    split_w1<<<(FIN * HID / 4 + 255) / 256, 256>>>(W1);
    split_w2<<<(HID * CC / 4 + 255) / 256, 256>>>(W2);

    // MLP on tensor cores
    cudaFuncSetAttribute(gemm1_tc, cudaFuncAttributeMaxDynamicSharedMemorySize, G1_SMEM);
    dim3 g1(HID / 128, (NN + 127) / 128);
    gemm1_tc<<<g1, 256, G1_SMEM>>>(b1);
    cudaFuncSetAttribute(gemm2_tc, cudaFuncAttributeMaxDynamicSharedMemorySize, G2_SMEM);
    gemm2_tc<<<(NN + 127) / 128, 256, G2_SMEM>>>(b2);

    // CSR build (by destination)
    zero_cnt <<<(NN + 255) / 256, 256>>>();
    count_deg<<<(EE + 255) / 256, 256>>>(dst);
    calc_dinv<<<(NN + 255) / 256, 256>>>();
    scan_rowptr<<<1, 1024>>>();
    fill_csr <<<(EE + 255) / 256, 256>>>(src, dst);

    // K fused propagation steps (ping-pong)
    const int threads = NN * 10;
    const int blocks  = (threads + 319) / 320;
    for (int it = 0; it < KIT; it++) {
        const float* zcur = (it == 0) ? p_h : ((it & 1) ? p_z1 : p_z0);
        float* znext = (it == KIT - 1) ? out : ((it & 1) ? p_z0 : p_z1);
        prop_step<<<blocks, 320>>>(zcur, znext);
    }
}